// round 3
// baseline (speedup 1.0000x reference)
#include <cuda_runtime.h>
#include <cuda_bf16.h>
#include <math.h>

// Problem constants (fixed by the reference)
#define EMB_DIM   100
#define CHUNK_M   50
#define SEQ_L     200
#define NWARPS    8
#define NTHREADS  (NWARPS * 32)
#define EPS       1e-8f
#define EPS2      (1e-8f * 1e-8f)

// One block per batch row b.
// Each warp handles l = warp, warp+NWARPS, ...  (25 iterations).
// Lanes 0..24 each own a float4 (4 consecutive embedding elements).
__global__ __launch_bounds__(NTHREADS)
void binclf_kernel(const int*   __restrict__ word_idxs,   // [B, L]
                   const float* __restrict__ emb_table,   // [V, 100]
                   const float* __restrict__ weights,     // [100, 1]
                   const float* __restrict__ attend_u,    // [2, 50] = 100 contiguous (chunk-major)
                   float*       __restrict__ out,         // [B, 1]
                   int B)
{
    const int b    = blockIdx.x;
    const int tid  = threadIdx.x;
    const int warp = tid >> 5;
    const int lane = tid & 31;

    // Element indices covered by this lane: e = lane*4 + j, j=0..3 (valid when lane < 25)
    const bool active = (lane < 25);
    const int  ebase  = lane * 4;

    // Per-element chunk membership (chunk 0: e < 50)
    bool c0[4];
    #pragma unroll
    for (int j = 0; j < 4; j++) c0[j] = (ebase + j) < CHUNK_M;

    // Load this lane's slice of attend_u and weights (same element ordering:
    // e = c*50 + m matches the reshape in the reference).
    float4 uv = make_float4(0.f, 0.f, 0.f, 0.f);
    float4 wv = make_float4(0.f, 0.f, 0.f, 0.f);
    if (active) {
        uv = reinterpret_cast<const float4*>(attend_u)[lane];
        wv = reinterpret_cast<const float4*>(weights)[lane];
    }
    float uarr[4] = {uv.x, uv.y, uv.z, uv.w};
    float warr[4] = {wv.x, wv.y, wv.z, wv.w};

    // Per-chunk ||u||^2 (warp butterfly reduce, every warp computes redundantly)
    float us0 = 0.f, us1 = 0.f;
    #pragma unroll
    for (int j = 0; j < 4; j++) {
        float q = uarr[j] * uarr[j];
        if (c0[j]) us0 += q; else us1 += q;
    }
    #pragma unroll
    for (int o = 16; o > 0; o >>= 1) {
        us0 += __shfl_xor_sync(0xffffffffu, us0, o);
        us1 += __shfl_xor_sync(0xffffffffu, us1, o);
    }
    const float uinv0 = rsqrtf(fmaxf(us0, EPS2));   // 1 / max(||u0||, eps)
    const float uinv1 = rsqrtf(fmaxf(us1, EPS2));

    // Accumulators
    float acc[4] = {0.f, 0.f, 0.f, 0.f};  // sum_l alpha * ch[e]  (per-lane elements)
    float A0 = 0.f, A1 = 0.f;             // sum_l alpha (per chunk); uniform across warp

    const int* idx_row = word_idxs + (size_t)b * SEQ_L;

    for (int l = warp; l < SEQ_L; l += NWARPS) {
        const int idx = idx_row[l];  // broadcast load (all lanes same addr)
        const float4* row = reinterpret_cast<const float4*>(emb_table + (size_t)idx * EMB_DIM);

        float4 v4 = make_float4(0.f, 0.f, 0.f, 0.f);
        if (active) v4 = __ldg(row + lane);
        float v[4] = {v4.x, v4.y, v4.z, v4.w};

        // Per-chunk sum-of-squares and dot with u
        float s0 = 0.f, s1 = 0.f, d0 = 0.f, d1 = 0.f;
        #pragma unroll
        for (int j = 0; j < 4; j++) {
            float sq = v[j] * v[j];
            float du = v[j] * uarr[j];
            if (c0[j]) { s0 += sq; d0 += du; }
            else       { s1 += sq; d1 += du; }
        }
        // Butterfly reduce 4 scalars across the warp
        #pragma unroll
        for (int o = 16; o > 0; o >>= 1) {
            s0 += __shfl_xor_sync(0xffffffffu, s0, o);
            s1 += __shfl_xor_sync(0xffffffffu, s1, o);
            d0 += __shfl_xor_sync(0xffffffffu, d0, o);
            d1 += __shfl_xor_sync(0xffffffffu, d1, o);
        }

        // cos_c = dot(ch, u) / (max(||ch||,eps) * max(||u||,eps)); alpha = exp(cos)
        const float a0 = __expf(d0 * rsqrtf(fmaxf(s0, EPS2)) * uinv0);
        const float a1 = __expf(d1 * rsqrtf(fmaxf(s1, EPS2)) * uinv1);

        A0 += a0;
        A1 += a1;
        #pragma unroll
        for (int j = 0; j < 4; j++) {
            float a = c0[j] ? a0 : a1;
            acc[j] = fmaf(a, v[j], acc[j]);
        }
    }

    // Per-lane projection with weights, split by chunk
    float p0 = 0.f, p1 = 0.f;
    #pragma unroll
    for (int j = 0; j < 4; j++) {
        float t = acc[j] * warr[j];
        if (c0[j]) p0 += t; else p1 += t;
    }
    #pragma unroll
    for (int o = 16; o > 0; o >>= 1) {
        p0 += __shfl_xor_sync(0xffffffffu, p0, o);
        p1 += __shfl_xor_sync(0xffffffffu, p1, o);
    }

    // Cross-warp combine in shared memory
    __shared__ float sm[NWARPS][4];
    if (lane == 0) {
        sm[warp][0] = p0;
        sm[warp][1] = p1;
        sm[warp][2] = A0;
        sm[warp][3] = A1;
    }
    __syncthreads();

    if (tid == 0) {
        float P0 = 0.f, P1 = 0.f, S0 = 0.f, S1 = 0.f;
        #pragma unroll
        for (int wdx = 0; wdx < NWARPS; wdx++) {
            P0 += sm[wdx][0];
            P1 += sm[wdx][1];
            S0 += sm[wdx][2];
            S1 += sm[wdx][3];
        }
        out[b] = P0 / S0 + P1 / S1;
    }
}

extern "C" void kernel_launch(void* const* d_in, const int* in_sizes, int n_in,
                              void* d_out, int out_size)
{
    const int*   word_idxs = (const int*)  d_in[0];  // [B, 200] int32
    const float* emb_table = (const float*)d_in[1];  // [100000, 100] f32
    const float* weights   = (const float*)d_in[2];  // [100, 1] f32
    const float* attend_u  = (const float*)d_in[3];  // [2, 50] f32
    float*       out       = (float*)d_out;          // [B, 1] f32

    const int B = in_sizes[0] / SEQ_L;

    binclf_kernel<<<B, NTHREADS>>>(word_idxs, emb_table, weights, attend_u, out, B);
}